// round 17
// baseline (speedup 1.0000x reference)
#include <cuda_runtime.h>
#include <cuda_fp16.h>
#include <cstdint>

#define N_NODES 50000
#define N_EDGES 1600000
#define DIM 128
#define NH 8
#define TILE_E 64
#define NTILES (N_EDGES / TILE_E)   // 25000
#define NPER 456                    // persistent CTAs (3 per SM x 152 SMs)
#define PADA 68                     // A tile row stride (half2 units)
#define PADB 136                    // B tile row stride (half2 units)
#define GEMM_BLKS 782               // ceil(50000/64)

// ---------------- scratch (static device globals: no alloc allowed) ----------
__device__ __half g_Q[(size_t)N_NODES * DIM];
__device__ __half g_K[(size_t)N_NODES * DIM];
__device__ __half g_V[(size_t)N_NODES * DIM];
__device__ int    g_cnt[N_NODES];
__device__ int    g_base[N_NODES + 1];
__device__ int4   g_edge4[N_EDGES];    // slot -> {src, dst, orig edge id, 0}
__device__ float  g_pscore[(size_t)N_EDGES * NH];   // 51 MB
__device__ int    g_idx64;

// ---------------- edge_index dtype detection (int64 vs int32) ----------------
__global__ void detect_idx_kernel(const void* idx) {
    const long long* p = (const long long*)idx;
    int is64 = 1;
    for (int i = 0; i < 64; i++) {
        long long v = p[i];
        if (v < 0 || v >= N_NODES) { is64 = 0; break; }
    }
    g_idx64 = is64;
}

// ---------------- single-block exclusive scan (1024 threads) ------------------
__global__ __launch_bounds__(1024)
void scan_kernel(const int* __restrict__ cnt, int* __restrict__ base) {
    __shared__ int wsum[32];
    const int tid = threadIdx.x;
    const int lane = tid & 31, wid = tid >> 5;
    const int CH = (N_NODES + 1023) / 1024;   // 49
    const int start = tid * CH;

    int s = 0;
    for (int i = 0; i < CH; i++) {
        const int idx = start + i;
        if (idx < N_NODES) s += cnt[idx];
    }
    int v = s;
#pragma unroll
    for (int d = 1; d < 32; d <<= 1) {
        int n = __shfl_up_sync(0xffffffffu, v, d);
        if (lane >= d) v += n;
    }
    if (lane == 31) wsum[wid] = v;
    __syncthreads();
    if (wid == 0) {
        int wv = wsum[lane];
#pragma unroll
        for (int d = 1; d < 32; d <<= 1) {
            int n = __shfl_up_sync(0xffffffffu, wv, d);
            if (lane >= d) wv += n;
        }
        wsum[lane] = wv;
    }
    __syncthreads();
    int run = v - s + (wid > 0 ? wsum[wid - 1] : 0);
    for (int i = 0; i < CH; i++) {
        const int idx = start + i;
        if (idx < N_NODES) { base[idx] = run; run += cnt[idx]; }
    }
    if (tid == 1023) base[N_NODES] = run;
}

// ---------------- convert: CSR slot assignment, single int4 store -------------
__global__ __launch_bounds__(256)
void convert_kernel(const void* __restrict__ eidx,
                    const int* __restrict__ base, int* __restrict__ cnt,
                    int4* __restrict__ edge4) {
    const int i = blockIdx.x * blockDim.x + threadIdx.x;
    if (i >= N_EDGES) return;
    int s, d;
    if (g_idx64) {
        const long long* p = (const long long*)eidx;
        s = (int)p[i];
        d = (int)p[(size_t)N_EDGES + i];
    } else {
        const int* p = (const int*)eidx;
        s = p[i];
        d = p[N_EDGES + i];
    }
    const int pp = base[d] + atomicAdd(&cnt[d], 1);
    edge4[pp] = make_int4(s, d, i, 0);
}

// ---------------- fp16 helpers -------------------------------------------------
__device__ __forceinline__ uint32_t f2h2(float lo, float hi) {
    __half2 h = __floats2half2_rn(lo, hi);
    return *(uint32_t*)&h;
}

__device__ __forceinline__ float4 h4_to_f4(uint2 raw) {
    const float2 lo = __half22float2(*(__half2*)&raw.x);
    const float2 hi = __half22float2(*(__half2*)&raw.y);
    return make_float4(lo.x, lo.y, hi.x, hi.y);
}

__device__ __forceinline__ void mma_f16(float* d, const uint32_t* a, const uint32_t* b) {
    asm volatile(
        "mma.sync.aligned.m16n8k16.row.col.f32.f16.f16.f32 "
        "{%0,%1,%2,%3}, {%4,%5,%6,%7}, {%8,%9}, {%0,%1,%2,%3};"
        : "+f"(d[0]), "+f"(d[1]), "+f"(d[2]), "+f"(d[3])
        : "r"(a[0]), "r"(a[1]), "r"(a[2]), "r"(a[3]),
          "r"(b[0]), "r"(b[1]));
}

// ---------------- projections (split-A fp16 mma) + hist, ONE launch -----------
__global__ __launch_bounds__(256, 2)
void sgemm3h_kernel(const float* __restrict__ A,
                    const float* __restrict__ WQ, const float* __restrict__ WK,
                    const float* __restrict__ WV,
                    __half* __restrict__ Q, __half* __restrict__ K,
                    __half* __restrict__ V, int M,
                    const void* __restrict__ eidx, int* __restrict__ cnt) {
    if (blockIdx.x >= 3 * GEMM_BLKS) {
        // ---- histogram path (grid-stride over edges) ----
        const bool idx64 = (g_idx64 != 0);
        const int stride = 304 * 256;
        for (int i = (blockIdx.x - 3 * GEMM_BLKS) * 256 + threadIdx.x;
             i < N_EDGES; i += stride) {
            int dst;
            if (idx64) dst = (int)__ldg((const long long*)eidx + (size_t)N_EDGES + i);
            else       dst = __ldg((const int*)eidx + N_EDGES + i);
            atomicAdd(&cnt[dst], 1);
        }
        return;
    }

    const int mat = blockIdx.x / GEMM_BLKS;
    const float* W = (mat == 0) ? WQ : (mat == 1) ? WK : WV;
    __half*      C = (mat == 0) ? Q  : (mat == 1) ? K  : V;
    const int m0 = (blockIdx.x % GEMM_BLKS) * 64;

    extern __shared__ uint32_t smem[];
    uint32_t* B2   = smem;                       // [64][PADB] half2 (W, k-paired)
    uint32_t* A2hi = B2 + 64 * PADB;             // [64][PADA] half2
    uint32_t* A2lo = A2hi + 64 * PADA;           // [64][PADA] half2

    const int tid  = threadIdx.x;
    const int lane = tid & 31;
    const int w    = tid >> 5;

    for (int idx = tid; idx < 64 * DIM; idx += 256) {
        const int kk = idx >> 7;
        const int n  = idx & 127;
        B2[kk * PADB + n] = f2h2(__ldg(W + (size_t)(2 * kk) * DIM + n),
                                 __ldg(W + (size_t)(2 * kk + 1) * DIM + n));
    }

#pragma unroll
    for (int i = 0; i < 8; i++) {
        const int r  = w + 8 * i;
        const int gr = m0 + r;
        float4 av = make_float4(0.f, 0.f, 0.f, 0.f);
        if (gr < M) av = __ldg((const float4*)(A + (size_t)gr * DIM) + lane);
        const __half hx = __float2half_rn(av.x), hy = __float2half_rn(av.y);
        const __half hz = __float2half_rn(av.z), hw = __float2half_rn(av.w);
        __half2 p0 = __halves2half2(hx, hy), p1 = __halves2half2(hz, hw);
        A2hi[r * PADA + lane * 2]     = *(uint32_t*)&p0;
        A2hi[r * PADA + lane * 2 + 1] = *(uint32_t*)&p1;
        A2lo[r * PADA + lane * 2]     = f2h2(av.x - __half2float(hx),
                                             av.y - __half2float(hy));
        A2lo[r * PADA + lane * 2 + 1] = f2h2(av.z - __half2float(hz),
                                             av.w - __half2float(hw));
    }
    __syncthreads();

    const int g  = lane >> 2;
    const int cc = lane & 3;
    const int mb = (w & 3) * 16;
    const int nb = (w >> 2) * 64;

    float acc[8][4];
#pragma unroll
    for (int nt = 0; nt < 8; nt++)
#pragma unroll
        for (int q = 0; q < 4; q++) acc[nt][q] = 0.0f;

#pragma unroll
    for (int ks = 0; ks < 8; ks++) {
        const int kk = 8 * ks + cc;
        uint32_t ah[4], al[4];
        ah[0] = A2hi[(mb + g) * PADA + kk];
        ah[1] = A2hi[(mb + g + 8) * PADA + kk];
        ah[2] = A2hi[(mb + g) * PADA + kk + 4];
        ah[3] = A2hi[(mb + g + 8) * PADA + kk + 4];
        al[0] = A2lo[(mb + g) * PADA + kk];
        al[1] = A2lo[(mb + g + 8) * PADA + kk];
        al[2] = A2lo[(mb + g) * PADA + kk + 4];
        al[3] = A2lo[(mb + g + 8) * PADA + kk + 4];
        uint32_t b[8][2];
#pragma unroll
        for (int nt = 0; nt < 8; nt++) {
            const int n = nb + 8 * nt + g;
            b[nt][0] = B2[kk * PADB + n];
            b[nt][1] = B2[(kk + 4) * PADB + n];
        }
#pragma unroll
        for (int nt = 0; nt < 8; nt++) {
            mma_f16(acc[nt], ah, b[nt]);
            mma_f16(acc[nt], al, b[nt]);
        }
    }

#pragma unroll
    for (int half = 0; half < 2; half++) {
        const int row = m0 + mb + g + 8 * half;
        if (row < M) {
#pragma unroll
            for (int nt = 0; nt < 8; nt++) {
                __half2 hv = __floats2half2_rn(acc[nt][2 * half], acc[nt][2 * half + 1]);
                *(__half2*)(C + (size_t)row * DIM + nb + 8 * nt + 2 * cc) = hv;
            }
        }
    }
}

// ---------------- fused edge kernel: accumulator-resident epilogue, 3 CTA/SM --
__global__ __launch_bounds__(256, 3)
void fused_edge_kernel(const float* __restrict__ ea,
                       const float* __restrict__ WE,
                       const __half* __restrict__ Q,
                       const __half* __restrict__ K,
                       const int4* __restrict__ edge4,
                       float* __restrict__ pscore) {
    extern __shared__ uint32_t smem[];
    uint32_t* B2 = smem;                         // [64][PADB] half2 (WE, k-paired)
    uint32_t* A2b[2];
    A2b[0] = B2 + 64 * PADB;                     // [64][PADA] half2, buffer 0
    A2b[1] = A2b[0] + 64 * PADA;                 // buffer 1

    const int tid  = threadIdx.x;
    const int lane = tid & 31;
    const int w    = tid >> 5;                   // 0..7

    for (int idx = tid; idx < 64 * DIM; idx += 256) {
        const int kk = idx >> 7;
        const int n  = idx & 127;
        const float w0 = __ldg(WE + (size_t)(2 * kk) * DIM + n);
        const float w1 = __ldg(WE + (size_t)(2 * kk + 1) * DIM + n);
        B2[kk * PADB + n] = f2h2(w0, w1);
    }

    // NTILES = 25000 = 456*54 + 376
    const int cnt = 54 + (blockIdx.x < (NTILES - NPER * 54) ? 1 : 0);

    float4 areg[8];
    auto prefetchA = [&](int tile) {
        const int e0 = tile * TILE_E;
        int myp = 0;
        if (lane < 8)
            myp = __ldg((const int*)(edge4 + e0 + w + 8 * lane) + 2);  // .z = pinv
#pragma unroll
        for (int i = 0; i < 8; i++) {
            const int eid = __shfl_sync(0xffffffffu, myp, i);
            areg[i] = __ldg((const float4*)(ea + (size_t)eid * DIM) + lane);
        }
    };

    prefetchA(blockIdx.x);   // prologue

    const int g  = lane >> 2;
    const int cc = lane & 3;
    const int mb = (w & 3) * 16;    // 16-edge block
    const int nb = (w >> 2) * 64;   // 64-col block (4 heads)
    const int hbase = (w >> 2) * 4; // global head base

    for (int j = 0; j < cnt; j++) {
        const int tile = blockIdx.x + j * NPER;
        const int e0   = tile * TILE_E;
        uint32_t* A2 = A2b[j & 1];

#pragma unroll
        for (int i = 0; i < 8; i++) {
            const int r = w + 8 * i;
            A2[r * PADA + lane * 2]     = f2h2(areg[i].x, areg[i].y);
            A2[r * PADA + lane * 2 + 1] = f2h2(areg[i].z, areg[i].w);
        }
        if (j + 1 < cnt) prefetchA(blockIdx.x + (j + 1) * NPER);

        int srcreg = 0, dstreg = 0;
        if (lane < 16) {
            const int2 sd = __ldg((const int2*)(edge4 + e0 + mb + lane));
            srcreg = sd.x;
            dstreg = sd.y;
        }

        __syncthreads();   // A(j) visible to all warps

        float acc[8][4];
#pragma unroll
        for (int nt = 0; nt < 8; nt++)
#pragma unroll
            for (int q = 0; q < 4; q++) acc[nt][q] = 0.0f;

#pragma unroll
        for (int ks = 0; ks < 8; ks++) {
            const int kk = 8 * ks + cc;
            uint32_t a[4];
            a[0] = A2[(mb + g) * PADA + kk];
            a[1] = A2[(mb + g + 8) * PADA + kk];
            a[2] = A2[(mb + g) * PADA + kk + 4];
            a[3] = A2[(mb + g + 8) * PADA + kk + 4];
            uint32_t b[8][2];
#pragma unroll
            for (int nt = 0; nt < 8; nt++) {
                const int n = nb + 8 * nt + g;
                b[nt][0] = B2[kk * PADB + n];
                b[nt][1] = B2[(kk + 4) * PADB + n];
            }
#pragma unroll
            for (int nt = 0; nt < 8; nt++)
                mma_f16(acc[nt], a, b[nt]);
        }

#pragma unroll
        for (int half = 0; half < 2; half++) {
            const int er  = g + 8 * half;
            const int src = __shfl_sync(0xffffffffu, srcreg, er);
            const int dst = __shfl_sync(0xffffffffu, dstreg, er);
            const __half* Kp = K + (size_t)src * DIM;
            const __half* Qp = Q + (size_t)dst * DIM;

            float hsum[4] = {0.f, 0.f, 0.f, 0.f};
#pragma unroll
            for (int chunk = 0; chunk < 2; chunk++) {
                float2 k2[4], q2[4];
#pragma unroll
                for (int t = 0; t < 4; t++) {
                    const int col = nb + 8 * (4 * chunk + t) + 2 * cc;
                    k2[t] = __half22float2(__ldg((const __half2*)(Kp + col)));
                    q2[t] = __half22float2(__ldg((const __half2*)(Qp + col)));
                }
#pragma unroll
                for (int t = 0; t < 4; t++) {
                    const int nt = 4 * chunk + t;
                    hsum[nt >> 1] += acc[nt][2 * half]     * k2[t].x * q2[t].x
                                   + acc[nt][2 * half + 1] * k2[t].y * q2[t].y;
                }
            }
#pragma unroll
            for (int h = 0; h < 4; h++) {
                hsum[h] += __shfl_xor_sync(0xffffffffu, hsum[h], 1);
                hsum[h] += __shfl_xor_sync(0xffffffffu, hsum[h], 2);
            }
            float s = 0.25f * hsum[cc];
            s = expf(fminf(fmaxf(s, -5.0f), 5.0f));
            pscore[(size_t)(e0 + mb + er) * NH + hbase + cc] = s;
        }
    }
}

// ---------------- gather: one warp per node, batched pscore/V streams ---------
__global__ __launch_bounds__(256)
void gather_kernel(const int* __restrict__ base,
                   const int4* __restrict__ edge4,
                   const float* __restrict__ pscore,
                   const __half* __restrict__ V,
                   float* __restrict__ out) {
    const int node = (blockIdx.x * blockDim.x + threadIdx.x) >> 5;
    const int lane = threadIdx.x & 31;
    if (node >= N_NODES) return;

    const int b = base[node];
    const int e = base[node + 1];
    const int h = lane >> 2;

    float4 acc = make_float4(0.f, 0.f, 0.f, 0.f);
    float z = 0.f;

    for (int cb = b; cb < e; cb += 32) {
        const int n = min(32, e - cb);
        int mysrc = 0;
        if (cb + lane < e) mysrc = __ldg((const int*)(edge4 + cb + lane));  // .x = src

        int i = 0;
        for (; i + 8 <= n; i += 8) {
            // batch pscore loads first (independent MLP stream)
            float sv[8];
#pragma unroll
            for (int u = 0; u < 8; u++)
                sv[u] = __ldg(pscore + (size_t)(cb + i + u) * NH + h);
            // then V loads + FMA
#pragma unroll
            for (int u = 0; u < 8; u++) {
                const int src = __shfl_sync(0xffffffffu, mysrc, i + u);
                const float4 v = h4_to_f4(__ldg((const uint2*)(V + (size_t)src * DIM) + lane));
                acc.x = fmaf(v.x, sv[u], acc.x);
                acc.y = fmaf(v.y, sv[u], acc.y);
                acc.z = fmaf(v.z, sv[u], acc.z);
                acc.w = fmaf(v.w, sv[u], acc.w);
                z += sv[u];
            }
        }
        for (; i < n; i++) {
            const int src = __shfl_sync(0xffffffffu, mysrc, i);
            const float s = __ldg(pscore + (size_t)(cb + i) * NH + h);
            const float4 v = h4_to_f4(__ldg((const uint2*)(V + (size_t)src * DIM) + lane));
            acc.x = fmaf(v.x, s, acc.x);
            acc.y = fmaf(v.y, s, acc.y);
            acc.z = fmaf(v.z, s, acc.z);
            acc.w = fmaf(v.w, s, acc.w);
            z += s;
        }
    }
    const float inv = 1.0f / (z + 1e-6f);
    *(float4*)(out + (size_t)node * DIM + lane * 4) =
        make_float4(acc.x * inv, acc.y * inv, acc.z * inv, acc.w * inv);
}

// ---------------- launch --------------------------------------------------------
extern "C" void kernel_launch(void* const* d_in, const int* in_sizes, int n_in,
                              void* d_out, int out_size) {
    const float* h   = (const float*)d_in[0];
    const float* ea  = (const float*)d_in[1];
    const float* WQ  = (const float*)d_in[2];
    const float* WK  = (const float*)d_in[3];
    const float* WV  = (const float*)d_in[4];
    const float* WE  = (const float*)d_in[5];
    const void*  eix = d_in[6];
    float* out = (float*)d_out;

    void *qp, *kp, *vp, *cntp, *basep, *e4p, *pscorep;
    cudaGetSymbolAddress(&qp,      g_Q);
    cudaGetSymbolAddress(&kp,      g_K);
    cudaGetSymbolAddress(&vp,      g_V);
    cudaGetSymbolAddress(&cntp,    g_cnt);
    cudaGetSymbolAddress(&basep,   g_base);
    cudaGetSymbolAddress(&e4p,     g_edge4);
    cudaGetSymbolAddress(&pscorep, g_pscore);

    detect_idx_kernel<<<1, 1>>>(eix);
    cudaMemsetAsync(cntp, 0, N_NODES * sizeof(int));

    const int smem_bytes = (64 * PADB + 2 * 64 * PADA) * 4;   // 69632

    // node projections + dst histogram in ONE launch
    cudaFuncSetAttribute(sgemm3h_kernel,
                         cudaFuncAttributeMaxDynamicSharedMemorySize, smem_bytes);
    sgemm3h_kernel<<<3 * GEMM_BLKS + 304, 256, smem_bytes>>>(
        h, WQ, WK, WV, (__half*)qp, (__half*)kp, (__half*)vp, N_NODES,
        eix, (int*)cntp);

    scan_kernel<<<1, 1024>>>((const int*)cntp, (int*)basep);
    cudaMemsetAsync(cntp, 0, N_NODES * sizeof(int));
    convert_kernel<<<(N_EDGES + 255) / 256, 256>>>(
        eix, (const int*)basep, (int*)cntp, (int4*)e4p);

    // fused persistent fp16 edge GEMM + accumulator-resident score (3 CTAs/SM)
    cudaFuncSetAttribute(fused_edge_kernel,
                         cudaFuncAttributeMaxDynamicSharedMemorySize, smem_bytes);
    fused_edge_kernel<<<NPER, 256, smem_bytes>>>(
        ea, WE, (const __half*)qp, (const __half*)kp,
        (const int4*)e4p, (float*)pscorep);

    // gather + normalize (one warp per node)
    gather_kernel<<<(N_NODES * 32 + 255) / 256, 256>>>(
        (const int*)basep, (const int4*)e4p, (const float*)pscorep,
        (const __half*)vp, out);
}